// round 15
// baseline (speedup 1.0000x reference)
#include <cuda_runtime.h>
#include <cuda_fp16.h>
#include <stdint.h>
#include <math.h>

// ============================================================================
// ContrastiveDistortion:
//   logits[a,b] = C0 - C1*(P_a.Q_b + s_a + s_b)   (rank-512 SYMMETRIC bilinear)
//   Single-term fp16 GEMM (K=512), upper-triangular tiles (528 CTAs), dual
//   row/col fused online LSE in log2 domain (bare EX2).
// R15: feat fused as a gemm prologue. CTAs 0..127 build 4x8 feature rows each
//   and bump per-block monotonic ready-counters; every CTA spin-waits on its
//   two blocks (target 16*(run+1); run id from a global ticket / 528 — replay
//   safe, no resets). Mainloop/epilogue and reduce byte-identical to R10.
// ============================================================================

namespace {
constexpr int BATCH = 2048;
constexpr int NROW  = 4096;
constexpr int DIM   = 128;
constexpr int KF    = 512;
constexpr int NBLK  = 32;             // 4096 / 128
constexpr int NPAIR = NBLK * (NBLK + 1) / 2;   // 528
constexpr int KSTAGES = KF / 64;      // 8
constexpr int ROWBYTES = KF * 2;      // 1024
constexpr uint32_t STG = 16384u;      // bytes per operand stage
constexpr int NRED = 32;              // reduce blocks
constexpr int FEATCTA = 128;          // CTAs doing feature build (<= min wave)

// log2-domain constants
constexpr float C0L2 = 923.3248262f;          // 640 * log2e
constexpr float C1L2 = 3.606737602f;          // 2.5 * log2e
constexpr float TO_ADD_L2 = -2.8188645e-4f;   // -1.9538879e-4 * log2e
constexpr float LN2 = 0.69314718055994531f;
constexpr float NEG_BIG = -1e30f;
}

__device__ __half g_P[(size_t)NROW * KF];   // 4.2 MB
__device__ __half g_Q[(size_t)NROW * KF];   // 4.2 MB
__device__ float g_s[NROW];
__device__ float g_Lpos[NROW];              // log2-domain
__device__ float g_partM[NBLK * NROW];      // log2-domain
__device__ float g_partS[NBLK * NROW];
__device__ float g_bsum[NRED];
__device__ int   g_cnt;                     // reduce finish counter (reset each run)
__device__ unsigned g_blkready[NBLK];       // monotonic: +16 per block per run
__device__ unsigned g_start;                // monotonic launch tickets

// ---------------------------------------------------------------------------
// helpers
// ---------------------------------------------------------------------------
__device__ __forceinline__ uint32_t smem_u32(const void* p) {
    uint32_t a;
    asm("{ .reg .u64 t; cvta.to.shared.u64 t, %1; cvt.u32.u64 %0, t; }" : "=r"(a) : "l"(p));
    return a;
}
__device__ __forceinline__ float ex2f(float x) {
    float r;
    asm("ex2.approx.ftz.f32 %0, %1;" : "=f"(r) : "f"(x));
    return r;
}
__device__ __forceinline__ float rcpf(float x) {
    float r;
    asm("rcp.approx.ftz.f32 %0, %1;" : "=f"(r) : "f"(x));
    return r;
}
__device__ __forceinline__ void cpasync16(uint32_t dst, const void* src) {
    asm volatile("cp.async.cg.shared.global [%0], [%1], 16;" :: "r"(dst), "l"(src) : "memory");
}
__device__ __forceinline__ void ldsm_x4(uint32_t* r, uint32_t addr) {
    asm volatile("ldmatrix.sync.aligned.m8n8.x4.shared.b16 {%0,%1,%2,%3}, [%4];"
                 : "=r"(r[0]), "=r"(r[1]), "=r"(r[2]), "=r"(r[3]) : "r"(addr));
}
__device__ __forceinline__ void mma16816(float* d, const uint32_t* a, uint32_t b0, uint32_t b1) {
    asm volatile(
        "mma.sync.aligned.m16n8k16.row.col.f32.f16.f16.f32 "
        "{%0,%1,%2,%3}, {%4,%5,%6,%7}, {%8,%9}, {%0,%1,%2,%3};"
        : "+f"(d[0]), "+f"(d[1]), "+f"(d[2]), "+f"(d[3])
        : "r"(a[0]), "r"(a[1]), "r"(a[2]), "r"(a[3]), "r"(b0), "r"(b1));
}

// ---------------------------------------------------------------------------
// Kernel: upper-triangular 128x128x512 fp16 mma.sync GEMM with fused feat
// prologue + dual LSE epilogue. grid = 528, 256 threads, 2 CTAs/SM.
// ---------------------------------------------------------------------------
__global__ __launch_bounds__(256, 2) void gemm_kernel(
        const float* __restrict__ mu_x,  const float* __restrict__ sig_x,
        const float* __restrict__ mu_p,  const float* __restrict__ sig_p) {
    extern __shared__ char smem[];
    __shared__ float scol[128], srow[128];          // pre-scaled: C0L2/2 - C1L2*s
    __shared__ float redM[128][4], redS[128][4];    // row-side across wn
    __shared__ float redCM[128][2], redCS[128][2];  // col-side across wm
    __shared__ unsigned s_run;

    const int tid = threadIdx.x;
    const int lane = tid & 31;
    const int warp = tid >> 5;
    const int bid = blockIdx.x;

    // run id from monotonic tickets (replays serialize -> tickets contiguous)
    if (tid == 0) s_run = atomicAdd(&g_start, 1u) / (unsigned)NPAIR;
    __syncthreads();
    const unsigned runid = s_run;

    // ---------------- feat prologue (CTAs 0..127: 4 groups of 8 rows) -------
    if (bid < FEATCTA) {
        const int d4 = lane * 4;
        #pragma unroll
        for (int it = 0; it < 4; ++it) {
            const int row = (bid * 4 + it) * 8 + warp;
            const float* mu_src = (row < BATCH) ? mu_x + (size_t)row * DIM
                                                : mu_p + (size_t)(row - BATCH) * DIM;
            const float* sg_src = (row < BATCH) ? sig_x + (size_t)row * DIM
                                                : sig_p + (size_t)(row - BATCH) * DIM;
            const float4 mu = __ldg(reinterpret_cast<const float4*>(mu_src + d4));
            const float4 sg = __ldg(reinterpret_cast<const float4*>(sg_src + d4));

            float mv[4] = {mu.x, mu.y, mu.z, mu.w};
            const float sv[4] = {sg.x, sg.y, sg.z, sg.w};
            float inv[4], w[4], tq[4];
            #pragma unroll
            for (int e = 0; e < 4; ++e) {
                const float var = sv[e] * sv[e];
                inv[e] = rcpf(var);
                w[e]   = var + mv[e] * mv[e];
                tq[e]  = mv[e] * inv[e];
            }

            __half* Prow = g_P + (size_t)row * KF;
            __half* Qrow = g_Q + (size_t)row * KF;
            auto pack4 = [](const float* v, float sc) -> uint2 {
                __half2 a = {__float2half_rn(v[0] * sc), __float2half_rn(v[1] * sc)};
                __half2 b = {__float2half_rn(v[2] * sc), __float2half_rn(v[3] * sc)};
                uint2 u;
                u.x = *reinterpret_cast<uint32_t*>(&a);
                u.y = *reinterpret_cast<uint32_t*>(&b);
                return u;
            };
            *reinterpret_cast<uint2*>(Prow +   0 + d4) = pack4(inv, 1.0f);
            *reinterpret_cast<uint2*>(Prow + 128 + d4) = pack4(w,   1.0f);
            *reinterpret_cast<uint2*>(Prow + 256 + d4) = pack4(tq,  1.0f);
            *reinterpret_cast<uint2*>(Prow + 384 + d4) = pack4(mv,  1.0f);
            *reinterpret_cast<uint2*>(Qrow +   0 + d4) = pack4(w,   1.0f);
            *reinterpret_cast<uint2*>(Qrow + 128 + d4) = pack4(inv, 1.0f);
            *reinterpret_cast<uint2*>(Qrow + 256 + d4) = pack4(mv, -2.0f);
            *reinterpret_cast<uint2*>(Qrow + 384 + d4) = pack4(tq, -2.0f);

            float part = tq[0] * mv[0] + tq[1] * mv[1] + tq[2] * mv[2] + tq[3] * mv[3];
            #pragma unroll
            for (int o = 16; o > 0; o >>= 1) part += __shfl_down_sync(0xffffffffu, part, o);
            if (lane == 0) g_s[row] = part;
        }
        __syncthreads();
        if (tid == 0) {
            __threadfence();   // publish feature stores before counters
            const int g0 = bid * 4;
            #pragma unroll
            for (int g = 0; g < 4; ++g)
                atomicAdd(&g_blkready[(g0 + g) >> 4], 1u);
        }
    }

    // ---------------- tile decode + readiness wait --------------------------
    int i = 0, tt = bid;
    while (tt >= NBLK - i) { tt -= NBLK - i; ++i; }
    const int j = i + tt;
    const bool isDiag = (i == j);
    const bool isPair = (j == i + 16);
    const int rowBase = i * 128, colBase = j * 128;

    if (tid == 0) {
        const unsigned target = 16u * (runid + 1u);
        volatile unsigned* br = g_blkready;
        while (br[i] < target) { }
        while (br[j] < target) { }
        __threadfence();       // acquire feature data
    }
    __syncthreads();

    if (tid < 128) {
        srow[tid] = 0.5f * C0L2 - C1L2 * g_s[rowBase + tid];
        scol[tid] = 0.5f * C0L2 - C1L2 * g_s[colBase + tid];
    }

    const uint32_t sb = smem_u32(smem);
    const char* gA = (const char*)g_P + (size_t)rowBase * ROWBYTES;
    const char* gB = (const char*)g_Q + (size_t)colBase * ROWBYTES;

    float acc[4][4][4];
    #pragma unroll
    for (int mt = 0; mt < 4; ++mt)
        #pragma unroll
        for (int nt = 0; nt < 4; ++nt)
            #pragma unroll
            for (int e = 0; e < 4; ++e) acc[mt][nt][e] = 0.0f;

    const int wm = warp >> 2;
    const int wn = warp & 3;
    const int l15 = lane & 15, lh = lane >> 4;
    const uint32_t xmask = (uint32_t)(lane & 7) << 4;
    uint32_t rowOffA[4], rowOffB[2], kx[4];
    #pragma unroll
    for (int mt = 0; mt < 4; ++mt) rowOffA[mt] = (uint32_t)(wm * 64 + mt * 16 + l15) * 128u;
    #pragma unroll
    for (int np = 0; np < 2; ++np) rowOffB[np] = (uint32_t)(wn * 32 + np * 16 + l15) * 128u;
    #pragma unroll
    for (int ks = 0; ks < 4; ++ks) kx[ks] = ((uint32_t)(ks * 32 + lh * 16)) ^ xmask;

    // stage layout: A stages [0,3*STG), B stages [3*STG, 6*STG)
    auto load_stage = [&](int kt, int s) {
        const uint32_t aD = sb + (uint32_t)s * STG;
        const uint32_t bD = sb + 3u * STG + (uint32_t)s * STG;
        #pragma unroll
        for (int u = 0; u < 4; ++u) {
            const int id = tid + 256 * u;
            const int r = id >> 3, l8 = id & 7;
            const uint32_t doff = (uint32_t)r * 128u + (uint32_t)((l8 ^ (r & 7)) << 4);
            const size_t soff = (size_t)r * ROWBYTES + (size_t)kt * 128 + (size_t)l8 * 16;
            cpasync16(aD + doff, gA + soff);
            cpasync16(bD + doff, gB + soff);
        }
        asm volatile("cp.async.commit_group;" ::: "memory");
    };

    load_stage(0, 0);
    load_stage(1, 1);

    for (int kt = 0; kt < KSTAGES; ++kt) {
        const int s = kt % 3;
        if (kt + 1 < KSTAGES) {
            asm volatile("cp.async.wait_group 1;" ::: "memory");
        } else {
            asm volatile("cp.async.wait_group 0;" ::: "memory");
        }
        __syncthreads();
        if (kt + 2 < KSTAGES) load_stage(kt + 2, (kt + 2) % 3);

        const uint32_t aB = sb + (uint32_t)s * STG;
        const uint32_t bB = sb + 3u * STG + (uint32_t)s * STG;
        #pragma unroll
        for (int ks = 0; ks < 4; ++ks) {
            uint32_t a[4][4], bt[2][4];
            #pragma unroll
            for (int mt = 0; mt < 4; ++mt) ldsm_x4(a[mt], aB + rowOffA[mt] + kx[ks]);
            #pragma unroll
            for (int np = 0; np < 2; ++np) ldsm_x4(bt[np], bB + rowOffB[np] + kx[ks]);
            #pragma unroll
            for (int mt = 0; mt < 4; ++mt)
                #pragma unroll
                for (int nt = 0; nt < 4; ++nt)
                    mma16816(acc[mt][nt], a[mt], bt[nt >> 1][nt & 1], bt[nt >> 1][(nt & 1) + 2]);
        }
    }

    // ---- transform acc to log2-domain logits ----
    const int qr = lane >> 2;
    const int qc = (lane & 3) << 1;
    #pragma unroll
    for (int mt = 0; mt < 4; ++mt) {
        #pragma unroll
        for (int nt = 0; nt < 4; ++nt) {
            #pragma unroll
            for (int e = 0; e < 4; ++e) {
                const int rl = wm * 64 + mt * 16 + ((e >> 1) << 3) + qr;
                const int cl = wn * 32 + nt * 8 + qc + (e & 1);
                float val = fmaf(-C1L2, acc[mt][nt][e], srow[rl] + scol[cl]);
                if (rl == cl) {
                    if (isDiag) {
                        val = NEG_BIG;
                    } else if (isPair) {
                        val += TO_ADD_L2;
                        g_Lpos[rowBase + rl] = val;
                        g_Lpos[colBase + cl] = val;
                    }
                }
                acc[mt][nt][e] = val;
            }
        }
    }

    // ---- row-side LSE (rows of block i; partial slot j) ----
    #pragma unroll
    for (int mt = 0; mt < 4; ++mt) {
        #pragma unroll
        for (int half = 0; half < 2; ++half) {
            const int rl = wm * 64 + mt * 16 + half * 8 + qr;
            float m = NEG_BIG;
            #pragma unroll
            for (int nt = 0; nt < 4; ++nt)
                #pragma unroll
                for (int jj = 0; jj < 2; ++jj)
                    m = fmaxf(m, acc[mt][nt][half * 2 + jj]);
            float su = 0.0f;
            #pragma unroll
            for (int nt = 0; nt < 4; ++nt)
                #pragma unroll
                for (int jj = 0; jj < 2; ++jj)
                    su += ex2f(acc[mt][nt][half * 2 + jj] - m);
            #pragma unroll
            for (int o = 1; o < 4; o <<= 1) {
                const float mo = __shfl_xor_sync(0xffffffffu, m, o);
                const float so = __shfl_xor_sync(0xffffffffu, su, o);
                const float nm = fmaxf(m, mo);
                su = su * ex2f(m - nm) + so * ex2f(mo - nm);
                m = nm;
            }
            if ((lane & 3) == 0) { redM[rl][wn] = m; redS[rl][wn] = su; }
        }
    }

    // ---- col-side LSE (rows of block j; partial slot i) ----
    if (!isDiag) {
        #pragma unroll
        for (int nt = 0; nt < 4; ++nt) {
            #pragma unroll
            for (int jj = 0; jj < 2; ++jj) {
                float m = NEG_BIG;
                #pragma unroll
                for (int mt = 0; mt < 4; ++mt)
                    #pragma unroll
                    for (int half = 0; half < 2; ++half)
                        m = fmaxf(m, acc[mt][nt][half * 2 + jj]);
                float su = 0.0f;
                #pragma unroll
                for (int mt = 0; mt < 4; ++mt)
                    #pragma unroll
                    for (int half = 0; half < 2; ++half)
                        su += ex2f(acc[mt][nt][half * 2 + jj] - m);
                #pragma unroll
                for (int o = 4; o < 32; o <<= 1) {
                    const float mo = __shfl_xor_sync(0xffffffffu, m, o);
                    const float so = __shfl_xor_sync(0xffffffffu, su, o);
                    const float nm = fmaxf(m, mo);
                    su = su * ex2f(m - nm) + so * ex2f(mo - nm);
                    m = nm;
                }
                if (lane < 4) {
                    const int cl = wn * 32 + nt * 8 + qc + jj;
                    redCM[cl][wm] = m;
                    redCS[cl][wm] = su;
                }
            }
        }
    }
    __syncthreads();

    if (tid < 128) {
        float M = redM[tid][0], S = redS[tid][0];
        #pragma unroll
        for (int q = 1; q < 4; ++q) {
            const float mj = redM[tid][q], sj = redS[tid][q];
            const float nm = fmaxf(M, mj);
            S = S * ex2f(M - nm) + sj * ex2f(mj - nm);
            M = nm;
        }
        g_partM[j * NROW + rowBase + tid] = M;
        g_partS[j * NROW + rowBase + tid] = S;

        if (!isDiag) {
            float Mc = redCM[tid][0], Sc = redCS[tid][0];
            const float m1 = redCM[tid][1], s1 = redCS[tid][1];
            const float nm = fmaxf(Mc, m1);
            Sc = Sc * ex2f(Mc - nm) + s1 * ex2f(m1 - nm);
            g_partM[i * NROW + colBase + tid] = nm;
            g_partS[i * NROW + colBase + tid] = Sc;
        }
    }
}

// ---------------------------------------------------------------------------
// Kernel 2: 32 blocks x 128 threads; per-row LSE merge, block partial sums,
// deterministic last-block finish. (byte-identical to R10)
// ---------------------------------------------------------------------------
__global__ __launch_bounds__(128) void reduce_kernel(float* __restrict__ out) {
    __shared__ float red[128];
    const int tid = threadIdx.x;
    const int row = blockIdx.x * 128 + tid;

    float mv[NBLK];
    float M = NEG_BIG;
    #pragma unroll
    for (int ch = 0; ch < NBLK; ++ch) {
        mv[ch] = g_partM[ch * NROW + row];
        M = fmaxf(M, mv[ch]);
    }
    float S = 0.0f;
    #pragma unroll
    for (int ch = 0; ch < NBLK; ++ch)
        S += g_partS[ch * NROW + row] * ex2f(mv[ch] - M);

    red[tid] = (M + __log2f(S)) - g_Lpos[row];
    __syncthreads();
    #pragma unroll
    for (int off = 64; off > 0; off >>= 1) {
        if (tid < off) red[tid] += red[tid + off];
        __syncthreads();
    }
    if (tid == 0) {
        g_bsum[blockIdx.x] = red[0];
        __threadfence();
        const int done = atomicAdd(&g_cnt, 1);
        if (done == NRED - 1) {
            float tot = 0.0f;
            #pragma unroll
            for (int k = 0; k < NRED; ++k) tot += g_bsum[k];
            out[0] = tot * LN2 / (float)NROW;
            g_cnt = 0;   // reset for next graph replay
        }
    }
}

// ---------------------------------------------------------------------------
extern "C" void kernel_launch(void* const* d_in, const int* in_sizes, int n_in,
                              void* d_out, int out_size) {
    (void)in_sizes; (void)n_in; (void)out_size;
    const float* mu_x  = (const float*)d_in[1];
    const float* sig_x = (const float*)d_in[2];
    const float* mu_p  = (const float*)d_in[3];
    const float* sig_p = (const float*)d_in[4];
    float* out = (float*)d_out;

    static bool attr_set = false;
    if (!attr_set) {
        cudaFuncSetAttribute(gemm_kernel, cudaFuncAttributeMaxDynamicSharedMemorySize, 98304);
        attr_set = true;
    }

    gemm_kernel<<<NPAIR, 256, 98304>>>(mu_x, sig_x, mu_p, sig_p);
    reduce_kernel<<<NRED, 128>>>(out);
}

// round 16
// speedup vs baseline: 1.1659x; 1.1659x over previous
#include <cuda_runtime.h>
#include <cuda_fp16.h>
#include <stdint.h>
#include <math.h>

// ============================================================================
// ContrastiveDistortion:
//   logits[a,b] = C0 - C1*(P_a.Q_b + s_a + s_b)   (rank-512 SYMMETRIC bilinear)
//   Single-term fp16 GEMM (K=512), upper-triangular tiles (528), dual row/col
//   fused online LSE in log2 domain (bare EX2).
// R16: R14 frozen except gemm grid = 296 CTAs x 2-tile loop (tile = bid,
//   bid+296) — removes the partial second wave's launch/drain transition.
//   feat (MLP-batched) and reduce byte-identical to R14.
// ============================================================================

namespace {
constexpr int BATCH = 2048;
constexpr int NROW  = 4096;
constexpr int DIM   = 128;
constexpr int KF    = 512;
constexpr int NBLK  = 32;             // 4096 / 128
constexpr int NPAIR = NBLK * (NBLK + 1) / 2;   // 528
constexpr int NGRID = 296;            // 148 SMs x 2 CTAs
constexpr int KSTAGES = KF / 64;      // 8
constexpr int ROWBYTES = KF * 2;      // 1024
constexpr uint32_t STG = 16384u;      // bytes per operand stage
constexpr int NRED = 32;              // reduce blocks

// log2-domain constants
constexpr float C0L2 = 923.3248262f;          // 640 * log2e
constexpr float C1L2 = 3.606737602f;          // 2.5 * log2e
constexpr float TO_ADD_L2 = -2.8188645e-4f;   // -1.9538879e-4 * log2e
constexpr float LN2 = 0.69314718055994531f;
constexpr float NEG_BIG = -1e30f;
}

__device__ __half g_P[(size_t)NROW * KF];   // 4.2 MB
__device__ __half g_Q[(size_t)NROW * KF];   // 4.2 MB
__device__ float g_s[NROW];
__device__ float g_Lpos[NROW];              // log2-domain
__device__ float g_partM[NBLK * NROW];      // log2-domain
__device__ float g_partS[NBLK * NROW];
__device__ float g_bsum[NRED];
__device__ int   g_cnt;                     // zero-init; reset by last block

// ---------------------------------------------------------------------------
// helpers
// ---------------------------------------------------------------------------
__device__ __forceinline__ uint32_t smem_u32(const void* p) {
    uint32_t a;
    asm("{ .reg .u64 t; cvta.to.shared.u64 t, %1; cvt.u32.u64 %0, t; }" : "=r"(a) : "l"(p));
    return a;
}
__device__ __forceinline__ float ex2f(float x) {
    float r;
    asm("ex2.approx.ftz.f32 %0, %1;" : "=f"(r) : "f"(x));
    return r;
}
__device__ __forceinline__ float rcpf(float x) {
    float r;
    asm("rcp.approx.ftz.f32 %0, %1;" : "=f"(r) : "f"(x));
    return r;
}
__device__ __forceinline__ void cpasync16(uint32_t dst, const void* src) {
    asm volatile("cp.async.cg.shared.global [%0], [%1], 16;" :: "r"(dst), "l"(src) : "memory");
}
__device__ __forceinline__ void ldsm_x4(uint32_t* r, uint32_t addr) {
    asm volatile("ldmatrix.sync.aligned.m8n8.x4.shared.b16 {%0,%1,%2,%3}, [%4];"
                 : "=r"(r[0]), "=r"(r[1]), "=r"(r[2]), "=r"(r[3]) : "r"(addr));
}
__device__ __forceinline__ void mma16816(float* d, const uint32_t* a, uint32_t b0, uint32_t b1) {
    asm volatile(
        "mma.sync.aligned.m16n8k16.row.col.f32.f16.f16.f32 "
        "{%0,%1,%2,%3}, {%4,%5,%6,%7}, {%8,%9}, {%0,%1,%2,%3};"
        : "+f"(d[0]), "+f"(d[1]), "+f"(d[2]), "+f"(d[3])
        : "r"(a[0]), "r"(a[1]), "r"(a[2]), "r"(a[3]), "r"(b0), "r"(b1));
}

// ---------------------------------------------------------------------------
// Kernel 1: build fp16 feature rows + row scalars s. (byte-identical to R14)
// 256 blocks x 256 threads; each warp handles 2 rows; loads batched up front.
// ---------------------------------------------------------------------------
__global__ __launch_bounds__(256) void feat_kernel(
        const float* __restrict__ mu_x,  const float* __restrict__ sig_x,
        const float* __restrict__ mu_p,  const float* __restrict__ sig_p) {
    const int t = threadIdx.x;
    const int lane = t & 31;
    const int warp = t >> 5;
    const int d4 = lane * 4;
    const int row0 = blockIdx.x * 16 + warp * 2;   // rows row0, row0+1

    float4 muv[2], sgv[2];
    #pragma unroll
    for (int r = 0; r < 2; ++r) {
        const int row = row0 + r;
        const float* mu_src = (row < BATCH) ? mu_x + (size_t)row * DIM
                                            : mu_p + (size_t)(row - BATCH) * DIM;
        const float* sg_src = (row < BATCH) ? sig_x + (size_t)row * DIM
                                            : sig_p + (size_t)(row - BATCH) * DIM;
        muv[r] = __ldg(reinterpret_cast<const float4*>(mu_src + d4));
        sgv[r] = __ldg(reinterpret_cast<const float4*>(sg_src + d4));
    }

    #pragma unroll
    for (int r = 0; r < 2; ++r) {
        const int row = row0 + r;
        float mv[4] = {muv[r].x, muv[r].y, muv[r].z, muv[r].w};
        const float sv[4] = {sgv[r].x, sgv[r].y, sgv[r].z, sgv[r].w};
        float inv[4], w[4], tq[4];
        #pragma unroll
        for (int e = 0; e < 4; ++e) {
            const float var = sv[e] * sv[e];
            inv[e] = rcpf(var);
            w[e]   = var + mv[e] * mv[e];
            tq[e]  = mv[e] * inv[e];
        }

        __half* Prow = g_P + (size_t)row * KF;
        __half* Qrow = g_Q + (size_t)row * KF;

        auto pack4 = [](const float* v, float sc) -> uint2 {
            __half2 a = {__float2half_rn(v[0] * sc), __float2half_rn(v[1] * sc)};
            __half2 b = {__float2half_rn(v[2] * sc), __float2half_rn(v[3] * sc)};
            uint2 u;
            u.x = *reinterpret_cast<uint32_t*>(&a);
            u.y = *reinterpret_cast<uint32_t*>(&b);
            return u;
        };

        // P blocks {inv, w, tq, mu};  Q blocks {w, inv, -2mu, -2tq}
        *reinterpret_cast<uint2*>(Prow +   0 + d4) = pack4(inv, 1.0f);
        *reinterpret_cast<uint2*>(Prow + 128 + d4) = pack4(w,   1.0f);
        *reinterpret_cast<uint2*>(Prow + 256 + d4) = pack4(tq,  1.0f);
        *reinterpret_cast<uint2*>(Prow + 384 + d4) = pack4(mv,  1.0f);
        *reinterpret_cast<uint2*>(Qrow +   0 + d4) = pack4(w,   1.0f);
        *reinterpret_cast<uint2*>(Qrow + 128 + d4) = pack4(inv, 1.0f);
        *reinterpret_cast<uint2*>(Qrow + 256 + d4) = pack4(mv, -2.0f);
        *reinterpret_cast<uint2*>(Qrow + 384 + d4) = pack4(tq, -2.0f);

        float part = tq[0] * mv[0] + tq[1] * mv[1] + tq[2] * mv[2] + tq[3] * mv[3];
        #pragma unroll
        for (int o = 16; o > 0; o >>= 1) part += __shfl_down_sync(0xffffffffu, part, o);
        if (lane == 0) g_s[row] = part;
    }
}

// ---------------------------------------------------------------------------
// Kernel 2: upper-triangular 128x128x512 fp16 mma.sync GEMM, fused dual LSE.
// grid = 296 CTAs; each runs tiles {bid, bid+296} (2nd iteration skipped when
// out of range). 256 threads, 3-stage cp.async ring, 2 CTAs/SM.
// ---------------------------------------------------------------------------
__global__ __launch_bounds__(256, 2) void gemm_kernel() {
    extern __shared__ char smem[];
    __shared__ float scol[128], srow[128];          // pre-scaled: C0L2/2 - C1L2*s
    __shared__ float redM[128][4], redS[128][4];    // row-side across wn
    __shared__ float redCM[128][2], redCS[128][2];  // col-side across wm

    const int tid = threadIdx.x;
    const int lane = tid & 31;
    const int warp = tid >> 5;
    const int wm = warp >> 2;
    const int wn = warp & 3;

    const uint32_t sb = smem_u32(smem);
    const int l15 = lane & 15, lh = lane >> 4;
    const uint32_t xmask = (uint32_t)(lane & 7) << 4;
    const int qr = lane >> 2;
    const int qc = (lane & 3) << 1;

    uint32_t rowOffA[4], rowOffB[2], kx[4];
    #pragma unroll
    for (int mt = 0; mt < 4; ++mt) rowOffA[mt] = (uint32_t)(wm * 64 + mt * 16 + l15) * 128u;
    #pragma unroll
    for (int np = 0; np < 2; ++np) rowOffB[np] = (uint32_t)(wn * 32 + np * 16 + l15) * 128u;
    #pragma unroll
    for (int ks = 0; ks < 4; ++ks) kx[ks] = ((uint32_t)(ks * 32 + lh * 16)) ^ xmask;

    for (int tile = blockIdx.x; tile < NPAIR; tile += NGRID) {
        // triangular decode: tile -> (i, j), i <= j
        int i = 0, tt = tile;
        while (tt >= NBLK - i) { tt -= NBLK - i; ++i; }
        const int j = i + tt;
        const bool isDiag = (i == j);
        const bool isPair = (j == i + 16);
        const int rowBase = i * 128, colBase = j * 128;

        __syncthreads();   // previous tile's readers of srow/scol/red* done
        if (tid < 128) {
            srow[tid] = 0.5f * C0L2 - C1L2 * g_s[rowBase + tid];
            scol[tid] = 0.5f * C0L2 - C1L2 * g_s[colBase + tid];
        }

        const char* gA = (const char*)g_P + (size_t)rowBase * ROWBYTES;
        const char* gB = (const char*)g_Q + (size_t)colBase * ROWBYTES;

        float acc[4][4][4];
        #pragma unroll
        for (int mt = 0; mt < 4; ++mt)
            #pragma unroll
            for (int nt = 0; nt < 4; ++nt)
                #pragma unroll
                for (int e = 0; e < 4; ++e) acc[mt][nt][e] = 0.0f;

        // stage layout: A stages [0,3*STG), B stages [3*STG, 6*STG)
        auto load_stage = [&](int kt, int s) {
            const uint32_t aD = sb + (uint32_t)s * STG;
            const uint32_t bD = sb + 3u * STG + (uint32_t)s * STG;
            #pragma unroll
            for (int u = 0; u < 4; ++u) {
                const int id = tid + 256 * u;
                const int r = id >> 3, l8 = id & 7;
                const uint32_t doff = (uint32_t)r * 128u + (uint32_t)((l8 ^ (r & 7)) << 4);
                const size_t soff = (size_t)r * ROWBYTES + (size_t)kt * 128 + (size_t)l8 * 16;
                cpasync16(aD + doff, gA + soff);
                cpasync16(bD + doff, gB + soff);
            }
            asm volatile("cp.async.commit_group;" ::: "memory");
        };

        load_stage(0, 0);
        load_stage(1, 1);

        for (int kt = 0; kt < KSTAGES; ++kt) {
            const int s = kt % 3;
            if (kt + 1 < KSTAGES) {
                asm volatile("cp.async.wait_group 1;" ::: "memory");
            } else {
                asm volatile("cp.async.wait_group 0;" ::: "memory");
            }
            __syncthreads();
            if (kt + 2 < KSTAGES) load_stage(kt + 2, (kt + 2) % 3);

            const uint32_t aB = sb + (uint32_t)s * STG;
            const uint32_t bB = sb + 3u * STG + (uint32_t)s * STG;
            #pragma unroll
            for (int ks = 0; ks < 4; ++ks) {
                uint32_t a[4][4], bt[2][4];
                #pragma unroll
                for (int mt = 0; mt < 4; ++mt) ldsm_x4(a[mt], aB + rowOffA[mt] + kx[ks]);
                #pragma unroll
                for (int np = 0; np < 2; ++np) ldsm_x4(bt[np], bB + rowOffB[np] + kx[ks]);
                #pragma unroll
                for (int mt = 0; mt < 4; ++mt)
                    #pragma unroll
                    for (int nt = 0; nt < 4; ++nt)
                        mma16816(acc[mt][nt], a[mt], bt[nt >> 1][nt & 1], bt[nt >> 1][(nt & 1) + 2]);
            }
        }

        // ---- transform acc to log2-domain logits ----
        #pragma unroll
        for (int mt = 0; mt < 4; ++mt) {
            #pragma unroll
            for (int nt = 0; nt < 4; ++nt) {
                #pragma unroll
                for (int e = 0; e < 4; ++e) {
                    const int rl = wm * 64 + mt * 16 + ((e >> 1) << 3) + qr;
                    const int cl = wn * 32 + nt * 8 + qc + (e & 1);
                    float val = fmaf(-C1L2, acc[mt][nt][e], srow[rl] + scol[cl]);
                    if (rl == cl) {
                        if (isDiag) {
                            val = NEG_BIG;
                        } else if (isPair) {
                            val += TO_ADD_L2;
                            g_Lpos[rowBase + rl] = val;
                            g_Lpos[colBase + cl] = val;
                        }
                    }
                    acc[mt][nt][e] = val;
                }
            }
        }

        // ---- row-side LSE (rows of block i; partial slot j) ----
        #pragma unroll
        for (int mt = 0; mt < 4; ++mt) {
            #pragma unroll
            for (int half = 0; half < 2; ++half) {
                const int rl = wm * 64 + mt * 16 + half * 8 + qr;
                float m = NEG_BIG;
                #pragma unroll
                for (int nt = 0; nt < 4; ++nt)
                    #pragma unroll
                    for (int jj = 0; jj < 2; ++jj)
                        m = fmaxf(m, acc[mt][nt][half * 2 + jj]);
                float su = 0.0f;
                #pragma unroll
                for (int nt = 0; nt < 4; ++nt)
                    #pragma unroll
                    for (int jj = 0; jj < 2; ++jj)
                        su += ex2f(acc[mt][nt][half * 2 + jj] - m);
                #pragma unroll
                for (int o = 1; o < 4; o <<= 1) {
                    const float mo = __shfl_xor_sync(0xffffffffu, m, o);
                    const float so = __shfl_xor_sync(0xffffffffu, su, o);
                    const float nm = fmaxf(m, mo);
                    su = su * ex2f(m - nm) + so * ex2f(mo - nm);
                    m = nm;
                }
                if ((lane & 3) == 0) { redM[rl][wn] = m; redS[rl][wn] = su; }
            }
        }

        // ---- col-side LSE (rows of block j; partial slot i) ----
        if (!isDiag) {
            #pragma unroll
            for (int nt = 0; nt < 4; ++nt) {
                #pragma unroll
                for (int jj = 0; jj < 2; ++jj) {
                    float m = NEG_BIG;
                    #pragma unroll
                    for (int mt = 0; mt < 4; ++mt)
                        #pragma unroll
                        for (int half = 0; half < 2; ++half)
                            m = fmaxf(m, acc[mt][nt][half * 2 + jj]);
                    float su = 0.0f;
                    #pragma unroll
                    for (int mt = 0; mt < 4; ++mt)
                        #pragma unroll
                        for (int half = 0; half < 2; ++half)
                            su += ex2f(acc[mt][nt][half * 2 + jj] - m);
                    #pragma unroll
                    for (int o = 4; o < 32; o <<= 1) {
                        const float mo = __shfl_xor_sync(0xffffffffu, m, o);
                        const float so = __shfl_xor_sync(0xffffffffu, su, o);
                        const float nm = fmaxf(m, mo);
                        su = su * ex2f(m - nm) + so * ex2f(mo - nm);
                        m = nm;
                    }
                    if (lane < 4) {
                        const int cl = wn * 32 + nt * 8 + qc + jj;
                        redCM[cl][wm] = m;
                        redCS[cl][wm] = su;
                    }
                }
            }
        }
        __syncthreads();

        if (tid < 128) {
            float M = redM[tid][0], S = redS[tid][0];
            #pragma unroll
            for (int q = 1; q < 4; ++q) {
                const float mj = redM[tid][q], sj = redS[tid][q];
                const float nm = fmaxf(M, mj);
                S = S * ex2f(M - nm) + sj * ex2f(mj - nm);
                M = nm;
            }
            g_partM[j * NROW + rowBase + tid] = M;
            g_partS[j * NROW + rowBase + tid] = S;

            if (!isDiag) {
                float Mc = redCM[tid][0], Sc = redCS[tid][0];
                const float m1 = redCM[tid][1], s1 = redCS[tid][1];
                const float nm = fmaxf(Mc, m1);
                Sc = Sc * ex2f(Mc - nm) + s1 * ex2f(m1 - nm);
                g_partM[i * NROW + colBase + tid] = nm;
                g_partS[i * NROW + colBase + tid] = Sc;
            }
        }
    }
}

// ---------------------------------------------------------------------------
// Kernel 3: 32 blocks x 128 threads; per-row LSE merge, block partial sums,
// deterministic last-block finish. (byte-identical to R14)
// ---------------------------------------------------------------------------
__global__ __launch_bounds__(128) void reduce_kernel(float* __restrict__ out) {
    __shared__ float red[128];
    const int tid = threadIdx.x;
    const int row = blockIdx.x * 128 + tid;

    float mv[NBLK];
    float M = NEG_BIG;
    #pragma unroll
    for (int ch = 0; ch < NBLK; ++ch) {
        mv[ch] = g_partM[ch * NROW + row];
        M = fmaxf(M, mv[ch]);
    }
    float S = 0.0f;
    #pragma unroll
    for (int ch = 0; ch < NBLK; ++ch)
        S += g_partS[ch * NROW + row] * ex2f(mv[ch] - M);

    red[tid] = (M + __log2f(S)) - g_Lpos[row];
    __syncthreads();
    #pragma unroll
    for (int off = 64; off > 0; off >>= 1) {
        if (tid < off) red[tid] += red[tid + off];
        __syncthreads();
    }
    if (tid == 0) {
        g_bsum[blockIdx.x] = red[0];
        __threadfence();
        const int done = atomicAdd(&g_cnt, 1);
        if (done == NRED - 1) {
            float tot = 0.0f;
            #pragma unroll
            for (int k = 0; k < NRED; ++k) tot += g_bsum[k];
            out[0] = tot * LN2 / (float)NROW;
            g_cnt = 0;   // reset for next graph replay
        }
    }
}

// ---------------------------------------------------------------------------
extern "C" void kernel_launch(void* const* d_in, const int* in_sizes, int n_in,
                              void* d_out, int out_size) {
    (void)in_sizes; (void)n_in; (void)out_size;
    const float* mu_x  = (const float*)d_in[1];
    const float* sig_x = (const float*)d_in[2];
    const float* mu_p  = (const float*)d_in[3];
    const float* sig_p = (const float*)d_in[4];
    float* out = (float*)d_out;

    static bool attr_set = false;
    if (!attr_set) {
        cudaFuncSetAttribute(gemm_kernel, cudaFuncAttributeMaxDynamicSharedMemorySize, 98304);
        attr_set = true;
    }

    feat_kernel<<<NROW / 16, 256>>>(mu_x, sig_x, mu_p, sig_p);
    gemm_kernel<<<NGRID, 256, 98304>>>();
    reduce_kernel<<<NRED, 128>>>(out);
}

// round 17
// speedup vs baseline: 1.2174x; 1.0442x over previous
#include <cuda_runtime.h>
#include <cuda_fp16.h>
#include <stdint.h>
#include <math.h>

// ============================================================================
// ContrastiveDistortion:
//   logits[a,b] = C0 - C1*(P_a.Q_b + s_a + s_b)   (rank-512 SYMMETRIC bilinear)
//   Single-term fp16 GEMM (K=512), upper-triangular tiles (528 CTAs), dual
//   row/col fused online LSE in log2 domain (bare EX2).
// R17: R14 structure (the 47.1us optimum). gemm + reduce byte-identical to
//   R14; feat reshaped to 512 CTAs x 128 threads for smoother SM spread.
// ============================================================================

namespace {
constexpr int BATCH = 2048;
constexpr int NROW  = 4096;
constexpr int DIM   = 128;
constexpr int KF    = 512;
constexpr int NBLK  = 32;             // 4096 / 128
constexpr int NPAIR = NBLK * (NBLK + 1) / 2;   // 528
constexpr int KSTAGES = KF / 64;      // 8
constexpr int ROWBYTES = KF * 2;      // 1024
constexpr uint32_t STG = 16384u;      // bytes per operand stage
constexpr int NRED = 32;              // reduce blocks

// log2-domain constants
constexpr float C0L2 = 923.3248262f;          // 640 * log2e
constexpr float C1L2 = 3.606737602f;          // 2.5 * log2e
constexpr float TO_ADD_L2 = -2.8188645e-4f;   // -1.9538879e-4 * log2e
constexpr float LN2 = 0.69314718055994531f;
constexpr float NEG_BIG = -1e30f;
}

__device__ __half g_P[(size_t)NROW * KF];   // 4.2 MB
__device__ __half g_Q[(size_t)NROW * KF];   // 4.2 MB
__device__ float g_s[NROW];
__device__ float g_Lpos[NROW];              // log2-domain
__device__ float g_partM[NBLK * NROW];      // log2-domain
__device__ float g_partS[NBLK * NROW];
__device__ float g_bsum[NRED];
__device__ int   g_cnt;                     // zero-init; reset by last block

// ---------------------------------------------------------------------------
// helpers
// ---------------------------------------------------------------------------
__device__ __forceinline__ uint32_t smem_u32(const void* p) {
    uint32_t a;
    asm("{ .reg .u64 t; cvta.to.shared.u64 t, %1; cvt.u32.u64 %0, t; }" : "=r"(a) : "l"(p));
    return a;
}
__device__ __forceinline__ float ex2f(float x) {
    float r;
    asm("ex2.approx.ftz.f32 %0, %1;" : "=f"(r) : "f"(x));
    return r;
}
__device__ __forceinline__ float rcpf(float x) {
    float r;
    asm("rcp.approx.ftz.f32 %0, %1;" : "=f"(r) : "f"(x));
    return r;
}
__device__ __forceinline__ void cpasync16(uint32_t dst, const void* src) {
    asm volatile("cp.async.cg.shared.global [%0], [%1], 16;" :: "r"(dst), "l"(src) : "memory");
}
__device__ __forceinline__ void ldsm_x4(uint32_t* r, uint32_t addr) {
    asm volatile("ldmatrix.sync.aligned.m8n8.x4.shared.b16 {%0,%1,%2,%3}, [%4];"
                 : "=r"(r[0]), "=r"(r[1]), "=r"(r[2]), "=r"(r[3]) : "r"(addr));
}
__device__ __forceinline__ void mma16816(float* d, const uint32_t* a, uint32_t b0, uint32_t b1) {
    asm volatile(
        "mma.sync.aligned.m16n8k16.row.col.f32.f16.f16.f32 "
        "{%0,%1,%2,%3}, {%4,%5,%6,%7}, {%8,%9}, {%0,%1,%2,%3};"
        : "+f"(d[0]), "+f"(d[1]), "+f"(d[2]), "+f"(d[3])
        : "r"(a[0]), "r"(a[1]), "r"(a[2]), "r"(a[3]), "r"(b0), "r"(b1));
}

// ---------------------------------------------------------------------------
// Kernel 1: build fp16 feature rows + row scalars s.
// 512 blocks x 128 threads (4 warps); each warp handles 2 rows; all 4 float4
// loads batched up front (MLP=4 per thread).
// ---------------------------------------------------------------------------
__global__ __launch_bounds__(128) void feat_kernel(
        const float* __restrict__ mu_x,  const float* __restrict__ sig_x,
        const float* __restrict__ mu_p,  const float* __restrict__ sig_p) {
    const int t = threadIdx.x;
    const int lane = t & 31;
    const int warp = t >> 5;
    const int d4 = lane * 4;
    const int row0 = blockIdx.x * 8 + warp * 2;   // rows row0, row0+1

    // batched loads (4 independent float4s in flight)
    float4 muv[2], sgv[2];
    #pragma unroll
    for (int r = 0; r < 2; ++r) {
        const int row = row0 + r;
        const float* mu_src = (row < BATCH) ? mu_x + (size_t)row * DIM
                                            : mu_p + (size_t)(row - BATCH) * DIM;
        const float* sg_src = (row < BATCH) ? sig_x + (size_t)row * DIM
                                            : sig_p + (size_t)(row - BATCH) * DIM;
        muv[r] = __ldg(reinterpret_cast<const float4*>(mu_src + d4));
        sgv[r] = __ldg(reinterpret_cast<const float4*>(sg_src + d4));
    }

    #pragma unroll
    for (int r = 0; r < 2; ++r) {
        const int row = row0 + r;
        float mv[4] = {muv[r].x, muv[r].y, muv[r].z, muv[r].w};
        const float sv[4] = {sgv[r].x, sgv[r].y, sgv[r].z, sgv[r].w};
        float inv[4], w[4], tq[4];
        #pragma unroll
        for (int e = 0; e < 4; ++e) {
            const float var = sv[e] * sv[e];
            inv[e] = rcpf(var);
            w[e]   = var + mv[e] * mv[e];
            tq[e]  = mv[e] * inv[e];
        }

        __half* Prow = g_P + (size_t)row * KF;
        __half* Qrow = g_Q + (size_t)row * KF;

        auto pack4 = [](const float* v, float sc) -> uint2 {
            __half2 a = {__float2half_rn(v[0] * sc), __float2half_rn(v[1] * sc)};
            __half2 b = {__float2half_rn(v[2] * sc), __float2half_rn(v[3] * sc)};
            uint2 u;
            u.x = *reinterpret_cast<uint32_t*>(&a);
            u.y = *reinterpret_cast<uint32_t*>(&b);
            return u;
        };

        // P blocks {inv, w, tq, mu};  Q blocks {w, inv, -2mu, -2tq}
        *reinterpret_cast<uint2*>(Prow +   0 + d4) = pack4(inv, 1.0f);
        *reinterpret_cast<uint2*>(Prow + 128 + d4) = pack4(w,   1.0f);
        *reinterpret_cast<uint2*>(Prow + 256 + d4) = pack4(tq,  1.0f);
        *reinterpret_cast<uint2*>(Prow + 384 + d4) = pack4(mv,  1.0f);
        *reinterpret_cast<uint2*>(Qrow +   0 + d4) = pack4(w,   1.0f);
        *reinterpret_cast<uint2*>(Qrow + 128 + d4) = pack4(inv, 1.0f);
        *reinterpret_cast<uint2*>(Qrow + 256 + d4) = pack4(mv, -2.0f);
        *reinterpret_cast<uint2*>(Qrow + 384 + d4) = pack4(tq, -2.0f);

        // s = sum_d mu^2 / var
        float part = tq[0] * mv[0] + tq[1] * mv[1] + tq[2] * mv[2] + tq[3] * mv[3];
        #pragma unroll
        for (int o = 16; o > 0; o >>= 1) part += __shfl_down_sync(0xffffffffu, part, o);
        if (lane == 0) g_s[row] = part;
    }
}

// ---------------------------------------------------------------------------
// Kernel 2: upper-triangular 128x128x512 fp16 mma.sync GEMM, fused dual LSE.
// grid = 528 pairs (i<=j), 256 threads, 3-stage cp.async ring, 2 CTAs/SM.
// (byte-identical to R14/R10 — the 47.1us configuration)
// ---------------------------------------------------------------------------
__global__ __launch_bounds__(256, 2) void gemm_kernel() {
    extern __shared__ char smem[];
    __shared__ float scol[128], srow[128];          // pre-scaled: C0L2/2 - C1L2*s
    __shared__ float redM[128][4], redS[128][4];    // row-side across wn
    __shared__ float redCM[128][2], redCS[128][2];  // col-side across wm

    const int tid = threadIdx.x;
    const int lane = tid & 31;
    const int warp = tid >> 5;
    const int wm = warp >> 2;
    const int wn = warp & 3;

    // triangular decode: bid -> (i, j), i <= j
    int i = 0, tt = blockIdx.x;
    while (tt >= NBLK - i) { tt -= NBLK - i; ++i; }
    const int j = i + tt;
    const bool isDiag = (i == j);
    const bool isPair = (j == i + 16);
    const int rowBase = i * 128, colBase = j * 128;

    if (tid < 128) {
        srow[tid] = 0.5f * C0L2 - C1L2 * g_s[rowBase + tid];
        scol[tid] = 0.5f * C0L2 - C1L2 * g_s[colBase + tid];
    }

    const uint32_t sb = smem_u32(smem);
    const char* gA = (const char*)g_P + (size_t)rowBase * ROWBYTES;
    const char* gB = (const char*)g_Q + (size_t)colBase * ROWBYTES;

    float acc[4][4][4];
    #pragma unroll
    for (int mt = 0; mt < 4; ++mt)
        #pragma unroll
        for (int nt = 0; nt < 4; ++nt)
            #pragma unroll
            for (int e = 0; e < 4; ++e) acc[mt][nt][e] = 0.0f;

    const int l15 = lane & 15, lh = lane >> 4;
    const uint32_t xmask = (uint32_t)(lane & 7) << 4;
    uint32_t rowOffA[4], rowOffB[2], kx[4];
    #pragma unroll
    for (int mt = 0; mt < 4; ++mt) rowOffA[mt] = (uint32_t)(wm * 64 + mt * 16 + l15) * 128u;
    #pragma unroll
    for (int np = 0; np < 2; ++np) rowOffB[np] = (uint32_t)(wn * 32 + np * 16 + l15) * 128u;
    #pragma unroll
    for (int ks = 0; ks < 4; ++ks) kx[ks] = ((uint32_t)(ks * 32 + lh * 16)) ^ xmask;

    // stage layout: A stages [0,3*STG), B stages [3*STG, 6*STG)
    auto load_stage = [&](int kt, int s) {
        const uint32_t aD = sb + (uint32_t)s * STG;
        const uint32_t bD = sb + 3u * STG + (uint32_t)s * STG;
        #pragma unroll
        for (int u = 0; u < 4; ++u) {
            const int id = tid + 256 * u;
            const int r = id >> 3, l8 = id & 7;
            const uint32_t doff = (uint32_t)r * 128u + (uint32_t)((l8 ^ (r & 7)) << 4);
            const size_t soff = (size_t)r * ROWBYTES + (size_t)kt * 128 + (size_t)l8 * 16;
            cpasync16(aD + doff, gA + soff);
            cpasync16(bD + doff, gB + soff);
        }
        asm volatile("cp.async.commit_group;" ::: "memory");
    };

    load_stage(0, 0);
    load_stage(1, 1);

    for (int kt = 0; kt < KSTAGES; ++kt) {
        const int s = kt % 3;
        if (kt + 1 < KSTAGES) {
            asm volatile("cp.async.wait_group 1;" ::: "memory");
        } else {
            asm volatile("cp.async.wait_group 0;" ::: "memory");
        }
        __syncthreads();
        if (kt + 2 < KSTAGES) load_stage(kt + 2, (kt + 2) % 3);

        const uint32_t aB = sb + (uint32_t)s * STG;
        const uint32_t bB = sb + 3u * STG + (uint32_t)s * STG;
        #pragma unroll
        for (int ks = 0; ks < 4; ++ks) {
            uint32_t a[4][4], bt[2][4];
            #pragma unroll
            for (int mt = 0; mt < 4; ++mt) ldsm_x4(a[mt], aB + rowOffA[mt] + kx[ks]);
            #pragma unroll
            for (int np = 0; np < 2; ++np) ldsm_x4(bt[np], bB + rowOffB[np] + kx[ks]);
            #pragma unroll
            for (int mt = 0; mt < 4; ++mt)
                #pragma unroll
                for (int nt = 0; nt < 4; ++nt)
                    mma16816(acc[mt][nt], a[mt], bt[nt >> 1][nt & 1], bt[nt >> 1][(nt & 1) + 2]);
        }
    }

    // ---- transform acc to log2-domain logits ----
    const int qr = lane >> 2;
    const int qc = (lane & 3) << 1;
    #pragma unroll
    for (int mt = 0; mt < 4; ++mt) {
        #pragma unroll
        for (int nt = 0; nt < 4; ++nt) {
            #pragma unroll
            for (int e = 0; e < 4; ++e) {
                const int rl = wm * 64 + mt * 16 + ((e >> 1) << 3) + qr;
                const int cl = wn * 32 + nt * 8 + qc + (e & 1);
                float val = fmaf(-C1L2, acc[mt][nt][e], srow[rl] + scol[cl]);
                if (rl == cl) {
                    if (isDiag) {
                        val = NEG_BIG;
                    } else if (isPair) {
                        val += TO_ADD_L2;
                        g_Lpos[rowBase + rl] = val;
                        g_Lpos[colBase + cl] = val;
                    }
                }
                acc[mt][nt][e] = val;
            }
        }
    }

    // ---- row-side LSE (rows of block i; partial slot j) ----
    #pragma unroll
    for (int mt = 0; mt < 4; ++mt) {
        #pragma unroll
        for (int half = 0; half < 2; ++half) {
            const int rl = wm * 64 + mt * 16 + half * 8 + qr;
            float m = NEG_BIG;
            #pragma unroll
            for (int nt = 0; nt < 4; ++nt)
                #pragma unroll
                for (int jj = 0; jj < 2; ++jj)
                    m = fmaxf(m, acc[mt][nt][half * 2 + jj]);
            float su = 0.0f;
            #pragma unroll
            for (int nt = 0; nt < 4; ++nt)
                #pragma unroll
                for (int jj = 0; jj < 2; ++jj)
                    su += ex2f(acc[mt][nt][half * 2 + jj] - m);
            #pragma unroll
            for (int o = 1; o < 4; o <<= 1) {
                const float mo = __shfl_xor_sync(0xffffffffu, m, o);
                const float so = __shfl_xor_sync(0xffffffffu, su, o);
                const float nm = fmaxf(m, mo);
                su = su * ex2f(m - nm) + so * ex2f(mo - nm);
                m = nm;
            }
            if ((lane & 3) == 0) { redM[rl][wn] = m; redS[rl][wn] = su; }
        }
    }

    // ---- col-side LSE (rows of block j; partial slot i) ----
    if (!isDiag) {
        #pragma unroll
        for (int nt = 0; nt < 4; ++nt) {
            #pragma unroll
            for (int jj = 0; jj < 2; ++jj) {
                float m = NEG_BIG;
                #pragma unroll
                for (int mt = 0; mt < 4; ++mt)
                    #pragma unroll
                    for (int half = 0; half < 2; ++half)
                        m = fmaxf(m, acc[mt][nt][half * 2 + jj]);
                float su = 0.0f;
                #pragma unroll
                for (int mt = 0; mt < 4; ++mt)
                    #pragma unroll
                    for (int half = 0; half < 2; ++half)
                        su += ex2f(acc[mt][nt][half * 2 + jj] - m);
                #pragma unroll
                for (int o = 4; o < 32; o <<= 1) {
                    const float mo = __shfl_xor_sync(0xffffffffu, m, o);
                    const float so = __shfl_xor_sync(0xffffffffu, su, o);
                    const float nm = fmaxf(m, mo);
                    su = su * ex2f(m - nm) + so * ex2f(mo - nm);
                    m = nm;
                }
                if (lane < 4) {
                    const int cl = wn * 32 + nt * 8 + qc + jj;
                    redCM[cl][wm] = m;
                    redCS[cl][wm] = su;
                }
            }
        }
    }
    __syncthreads();

    if (tid < 128) {
        float M = redM[tid][0], S = redS[tid][0];
        #pragma unroll
        for (int q = 1; q < 4; ++q) {
            const float mj = redM[tid][q], sj = redS[tid][q];
            const float nm = fmaxf(M, mj);
            S = S * ex2f(M - nm) + sj * ex2f(mj - nm);
            M = nm;
        }
        g_partM[j * NROW + rowBase + tid] = M;
        g_partS[j * NROW + rowBase + tid] = S;

        if (!isDiag) {
            float Mc = redCM[tid][0], Sc = redCS[tid][0];
            const float m1 = redCM[tid][1], s1 = redCS[tid][1];
            const float nm = fmaxf(Mc, m1);
            Sc = Sc * ex2f(Mc - nm) + s1 * ex2f(m1 - nm);
            g_partM[i * NROW + colBase + tid] = nm;
            g_partS[i * NROW + colBase + tid] = Sc;
        }
    }
}

// ---------------------------------------------------------------------------
// Kernel 3: 32 blocks x 128 threads; per-row LSE merge, block partial sums,
// deterministic last-block finish. (byte-identical to R14/R10)
// ---------------------------------------------------------------------------
__global__ __launch_bounds__(128) void reduce_kernel(float* __restrict__ out) {
    __shared__ float red[128];
    const int tid = threadIdx.x;
    const int row = blockIdx.x * 128 + tid;

    float mv[NBLK];
    float M = NEG_BIG;
    #pragma unroll
    for (int ch = 0; ch < NBLK; ++ch) {
        mv[ch] = g_partM[ch * NROW + row];
        M = fmaxf(M, mv[ch]);
    }
    float S = 0.0f;
    #pragma unroll
    for (int ch = 0; ch < NBLK; ++ch)
        S += g_partS[ch * NROW + row] * ex2f(mv[ch] - M);

    red[tid] = (M + __log2f(S)) - g_Lpos[row];
    __syncthreads();
    #pragma unroll
    for (int off = 64; off > 0; off >>= 1) {
        if (tid < off) red[tid] += red[tid + off];
        __syncthreads();
    }
    if (tid == 0) {
        g_bsum[blockIdx.x] = red[0];
        __threadfence();
        const int done = atomicAdd(&g_cnt, 1);
        if (done == NRED - 1) {
            float tot = 0.0f;
            #pragma unroll
            for (int k = 0; k < NRED; ++k) tot += g_bsum[k];
            out[0] = tot * LN2 / (float)NROW;
            g_cnt = 0;   // reset for next graph replay
        }
    }
}

// ---------------------------------------------------------------------------
extern "C" void kernel_launch(void* const* d_in, const int* in_sizes, int n_in,
                              void* d_out, int out_size) {
    (void)in_sizes; (void)n_in; (void)out_size;
    const float* mu_x  = (const float*)d_in[1];
    const float* sig_x = (const float*)d_in[2];
    const float* mu_p  = (const float*)d_in[3];
    const float* sig_p = (const float*)d_in[4];
    float* out = (float*)d_out;

    static bool attr_set = false;
    if (!attr_set) {
        cudaFuncSetAttribute(gemm_kernel, cudaFuncAttributeMaxDynamicSharedMemorySize, 98304);
        attr_set = true;
    }

    feat_kernel<<<NROW / 8, 128>>>(mu_x, sig_x, mu_p, sig_p);
    gemm_kernel<<<NPAIR, 256, 98304>>>();
    reduce_kernel<<<NRED, 128>>>(out);
}